// round 10
// baseline (speedup 1.0000x reference)
#include <cuda_runtime.h>

// HGCNLayer: KG scatter-mean + sparse user aggregation.
// Inputs (JAX default config: "int64" arrays are int32):
//  0: entity_emb float32 [N_ENT*128], 1: edge_index int32 [2*E],
//  2: edge_type int32 [E], 3: interact_rows int32 [NNZ],
//  4: interact_cols int32 [NNZ], 5: interact_vals float32 [NNZ],
//  (optional n_users scalar), last: weight float32 [R*128]
// Output: [entity_agg (N_ENT*128) | user_agg (N_USR*128)] float32
//
// Strategy: counts-first. Pass 1 computes per-head edge counts; pass 2 inverts
// them; the fused scatter kernel multiplies each edge contribution by
// inv_count[head] before the red.v4, so no finalize read-modify-write pass
// over the 51 MB entity region is needed.

#define DD 128
#define MAX_ENTITIES 100000
#define MAX_RELS 32

__device__ float g_counts[MAX_ENTITIES];  // counts, then inverted in place

__device__ __forceinline__ void red_add_v4(float* p, float4 v) {
    asm volatile("red.global.add.v4.f32 [%0], {%1, %2, %3, %4};"
                 :: "l"(p), "f"(v.x), "f"(v.y), "f"(v.z), "f"(v.w)
                 : "memory");
}

__device__ __forceinline__ void red_add_f32(float* p, float v) {
    asm volatile("red.global.add.f32 [%0], %1;" :: "l"(p), "f"(v) : "memory");
}

// Pass 1: per-head edge counts (4 edges per thread for index-load efficiency).
__global__ void hgcn_count_kernel(const int* __restrict__ edge_index, int n_edges) {
    int base = (blockIdx.x * blockDim.x + threadIdx.x) * 4;
    #pragma unroll
    for (int j = 0; j < 4; j++) {
        int e = base + j;
        if (e < n_edges) red_add_f32(&g_counts[edge_index[e]], 1.0f);
    }
}

// Pass 2: counts -> 1/max(count,1), in place.
__global__ void hgcn_invert_kernel(int n_ent) {
    int i = blockIdx.x * blockDim.x + threadIdx.x;
    if (i < n_ent) g_counts[i] = 1.0f / fmaxf(g_counts[i], 1.0f);
}

// Fused scatter kernel. Blocks [0, edge_blocks) process edges (2 per warp,
// weight table staged in smem, contribution pre-scaled by inv count);
// remaining blocks process interactions (4 per warp).
__global__ void hgcn_scatter_kernel(const float* __restrict__ emb,
                                    const int* __restrict__ edge_index,
                                    const int* __restrict__ edge_type,
                                    const float* __restrict__ weight,
                                    const int* __restrict__ rows,
                                    const int* __restrict__ cols,
                                    const float* __restrict__ vals,
                                    float* __restrict__ ent_out,
                                    float* __restrict__ user_out,
                                    int n_edges, int n_rel, int nnz,
                                    int edge_blocks) {
    __shared__ float4 sw[MAX_RELS * 32];
    int lane = threadIdx.x & 31;
    int wib  = threadIdx.x >> 5;            // warp in block
    int wpb  = blockDim.x >> 5;             // warps per block

    if (blockIdx.x < edge_blocks) {
        // ---- edge half ----
        int nw4 = n_rel * 32;
        for (int i = threadIdx.x; i < nw4; i += blockDim.x)
            sw[i] = ((const float4*)weight)[i];
        __syncthreads();

        int warp = blockIdx.x * wpb + wib;
        int e0 = warp * 2;
        if (e0 >= n_edges) return;
        int e1 = e0 + 1;
        bool has1 = e1 < n_edges;

        int h0 = edge_index[e0];
        int t0 = edge_index[n_edges + e0];
        int r0 = edge_type[e0] - 1;
        int h1 = 0, t1 = 0, r1 = 0;
        if (has1) {
            h1 = edge_index[e1];
            t1 = edge_index[n_edges + e1];
            r1 = edge_type[e1] - 1;
        }

        float4 a0 = __ldg((const float4*)(emb + (long)t0 * DD) + lane);
        float4 a1 = make_float4(0.f, 0.f, 0.f, 0.f);
        if (has1) a1 = __ldg((const float4*)(emb + (long)t1 * DD) + lane);
        float inv0 = g_counts[h0];
        float inv1 = has1 ? g_counts[h1] : 0.f;

        float4 b0 = sw[r0 * 32 + lane];
        float4 v0 = make_float4(a0.x * b0.x * inv0, a0.y * b0.y * inv0,
                                a0.z * b0.z * inv0, a0.w * b0.w * inv0);
        red_add_v4(ent_out + (long)h0 * DD + lane * 4, v0);
        if (has1) {
            float4 b1 = sw[r1 * 32 + lane];
            float4 v1 = make_float4(a1.x * b1.x * inv1, a1.y * b1.y * inv1,
                                    a1.z * b1.z * inv1, a1.w * b1.w * inv1);
            red_add_v4(ent_out + (long)h1 * DD + lane * 4, v1);
        }
    } else {
        // ---- user half: 4 nnz per warp ----
        int warp = (blockIdx.x - edge_blocks) * wpb + wib;
        int base = warp * 4;
        if (base >= nnz) return;

        int   u[4], c[4];
        float s[4];
        int cnt = min(4, nnz - base);
        #pragma unroll
        for (int j = 0; j < 4; j++) {
            int i = base + ((j < cnt) ? j : 0);
            u[j] = rows[i]; c[j] = cols[i]; s[j] = vals[i];
        }

        float4 a[4];
        #pragma unroll
        for (int j = 0; j < 4; j++)
            a[j] = __ldg((const float4*)(emb + (long)c[j] * DD) + lane);

        #pragma unroll
        for (int j = 0; j < 4; j++) {
            if (j < cnt) {
                float4 v = make_float4(a[j].x * s[j], a[j].y * s[j],
                                       a[j].z * s[j], a[j].w * s[j]);
                red_add_v4(user_out + (long)u[j] * DD + lane * 4, v);
            }
        }
    }
}

extern "C" void kernel_launch(void* const* d_in, const int* in_sizes, int n_in,
                              void* d_out, int out_size) {
    const float* emb    = (const float*)d_in[0];
    const int*   ei     = (const int*)d_in[1];
    const int*   et     = (const int*)d_in[2];
    const int*   irows  = (const int*)d_in[3];
    const int*   icols  = (const int*)d_in[4];
    const float* ivals  = (const float*)d_in[5];
    const float* weight = (const float*)d_in[n_in - 1];

    int n_entities = in_sizes[0] / DD;
    int n_edges    = in_sizes[2];
    int nnz        = in_sizes[5];
    int n_rel      = in_sizes[n_in - 1] / DD;
    if (n_rel > MAX_RELS) n_rel = MAX_RELS;

    float* ent_out  = (float*)d_out;
    float* user_out = (float*)d_out + (long)n_entities * DD;

    // Zero output (DMA fill) and counts scratch.
    cudaMemsetAsync(d_out, 0, (size_t)out_size * sizeof(float));
    void* counts_addr = nullptr;
    cudaGetSymbolAddress(&counts_addr, g_counts);
    cudaMemsetAsync(counts_addr, 0, (size_t)n_entities * sizeof(float));

    // Pass 1: counts. Pass 2: invert.
    {
        int threads = 256;
        int per_block = threads * 4;
        hgcn_count_kernel<<<(n_edges + per_block - 1) / per_block, threads>>>(ei, n_edges);
        hgcn_invert_kernel<<<(n_entities + 255) / 256, 256>>>(n_entities);
    }

    // Fused scatter: edge blocks then user blocks in one grid.
    {
        int threads = 256;                         // 8 warps
        int edge_blocks = (n_edges + 15) / 16;     // 2 edges/warp
        int user_blocks = (nnz + 31) / 32;         // 4 nnz/warp
        hgcn_scatter_kernel<<<edge_blocks + user_blocks, threads>>>(
            emb, ei, et, weight, irows, icols, ivals,
            ent_out, user_out, n_edges, n_rel, nnz, edge_blocks);
    }
}

// round 11
// speedup vs baseline: 1.0553x; 1.0553x over previous
#include <cuda_runtime.h>

// HGCNLayer: KG scatter-mean + sparse user aggregation.
// Inputs (JAX default config: "int64" arrays are int32):
//  0: entity_emb float32 [N_ENT*128], 1: edge_index int32 [2*E],
//  2: edge_type int32 [E], 3: interact_rows int32 [NNZ],
//  4: interact_cols int32 [NNZ], 5: interact_vals float32 [NNZ],
//  (optional n_users scalar), last: weight float32 [R*128]
// Output: [entity_agg (N_ENT*128) | user_agg (N_USR*128)] float32
//
// Counts-first strategy (edge contributions pre-scaled by 1/deg so no
// finalize pass). Scatter kernel uses persistent-style strided warps so the
// 16 KB smem weight staging amortizes over ~64 edges/warp instead of 2
// (R10 spent ~600 MB of L2 traffic on re-staging weight per tiny block).

#define DD 128
#define MAX_ENTITIES 100000
#define MAX_RELS 32

__device__ float g_counts[MAX_ENTITIES];  // counts, then inverted in place

__device__ __forceinline__ void red_add_v4(float* p, float4 v) {
    asm volatile("red.global.add.v4.f32 [%0], {%1, %2, %3, %4};"
                 :: "l"(p), "f"(v.x), "f"(v.y), "f"(v.z), "f"(v.w)
                 : "memory");
}

__device__ __forceinline__ void red_add_f32(float* p, float v) {
    asm volatile("red.global.add.f32 [%0], %1;" :: "l"(p), "f"(v) : "memory");
}

// Pass 1: per-head edge counts (4 edges per thread).
__global__ void hgcn_count_kernel(const int* __restrict__ edge_index, int n_edges) {
    int base = (blockIdx.x * blockDim.x + threadIdx.x) * 4;
    #pragma unroll
    for (int j = 0; j < 4; j++) {
        int e = base + j;
        if (e < n_edges) red_add_f32(&g_counts[edge_index[e]], 1.0f);
    }
}

// Pass 2: counts -> 1/max(count,1), in place.
__global__ void hgcn_invert_kernel(int n_ent) {
    int i = blockIdx.x * blockDim.x + threadIdx.x;
    if (i < n_ent) g_counts[i] = 1.0f / fmaxf(g_counts[i], 1.0f);
}

// Fused scatter kernel, persistent-style strided warps.
// Blocks [0, edge_blocks): edge aggregation (2 edges/iter/warp, weight in smem,
// contribution pre-scaled by inverse head count).
// Blocks [edge_blocks, ...): user aggregation (4 nnz/iter/warp).
__global__ void hgcn_scatter_kernel(const float* __restrict__ emb,
                                    const int* __restrict__ edge_index,
                                    const int* __restrict__ edge_type,
                                    const float* __restrict__ weight,
                                    const int* __restrict__ rows,
                                    const int* __restrict__ cols,
                                    const float* __restrict__ vals,
                                    float* __restrict__ ent_out,
                                    float* __restrict__ user_out,
                                    int n_edges, int n_rel, int nnz,
                                    int edge_blocks, int user_blocks) {
    __shared__ float4 sw[MAX_RELS * 32];
    int lane = threadIdx.x & 31;
    int wib  = threadIdx.x >> 5;
    int wpb  = blockDim.x >> 5;

    if (blockIdx.x < edge_blocks) {
        // ---- edge section ----
        int nw4 = n_rel * 32;
        for (int i = threadIdx.x; i < nw4; i += blockDim.x)
            sw[i] = ((const float4*)weight)[i];
        __syncthreads();

        int warp   = blockIdx.x * wpb + wib;
        int nwarps = edge_blocks * wpb;
        long stride = (long)nwarps * 2;

        for (long e0 = (long)warp * 2; e0 < n_edges; e0 += stride) {
            long e1 = e0 + 1;
            bool has1 = e1 < n_edges;

            int h0 = edge_index[e0];
            int t0 = edge_index[n_edges + e0];
            int r0 = edge_type[e0] - 1;
            int h1 = 0, t1 = 0, r1 = 0;
            if (has1) {
                h1 = edge_index[e1];
                t1 = edge_index[n_edges + e1];
                r1 = edge_type[e1] - 1;
            }

            float4 a0 = __ldg((const float4*)(emb + (long)t0 * DD) + lane);
            float4 a1 = make_float4(0.f, 0.f, 0.f, 0.f);
            if (has1) a1 = __ldg((const float4*)(emb + (long)t1 * DD) + lane);
            float inv0 = g_counts[h0];
            float inv1 = has1 ? g_counts[h1] : 0.f;

            float4 b0 = sw[r0 * 32 + lane];
            float4 v0 = make_float4(a0.x * b0.x * inv0, a0.y * b0.y * inv0,
                                    a0.z * b0.z * inv0, a0.w * b0.w * inv0);
            red_add_v4(ent_out + (long)h0 * DD + lane * 4, v0);
            if (has1) {
                float4 b1 = sw[r1 * 32 + lane];
                float4 v1 = make_float4(a1.x * b1.x * inv1, a1.y * b1.y * inv1,
                                        a1.z * b1.z * inv1, a1.w * b1.w * inv1);
                red_add_v4(ent_out + (long)h1 * DD + lane * 4, v1);
            }
        }
    } else {
        // ---- user section: 4 nnz per warp-iteration ----
        int warp   = (blockIdx.x - edge_blocks) * wpb + wib;
        int nwarps = user_blocks * wpb;
        long stride = (long)nwarps * 4;

        for (long base = (long)warp * 4; base < nnz; base += stride) {
            int cnt = (int)min((long)4, (long)nnz - base);

            int   u[4], c[4];
            float s[4];
            #pragma unroll
            for (int j = 0; j < 4; j++) {
                long i = base + ((j < cnt) ? j : 0);
                u[j] = rows[i]; c[j] = cols[i]; s[j] = vals[i];
            }

            float4 a[4];
            #pragma unroll
            for (int j = 0; j < 4; j++)
                a[j] = __ldg((const float4*)(emb + (long)c[j] * DD) + lane);

            #pragma unroll
            for (int j = 0; j < 4; j++) {
                if (j < cnt) {
                    float4 v = make_float4(a[j].x * s[j], a[j].y * s[j],
                                           a[j].z * s[j], a[j].w * s[j]);
                    red_add_v4(user_out + (long)u[j] * DD + lane * 4, v);
                }
            }
        }
    }
}

extern "C" void kernel_launch(void* const* d_in, const int* in_sizes, int n_in,
                              void* d_out, int out_size) {
    const float* emb    = (const float*)d_in[0];
    const int*   ei     = (const int*)d_in[1];
    const int*   et     = (const int*)d_in[2];
    const int*   irows  = (const int*)d_in[3];
    const int*   icols  = (const int*)d_in[4];
    const float* ivals  = (const float*)d_in[5];
    const float* weight = (const float*)d_in[n_in - 1];

    int n_entities = in_sizes[0] / DD;
    int n_edges    = in_sizes[2];
    int nnz        = in_sizes[5];
    int n_rel      = in_sizes[n_in - 1] / DD;
    if (n_rel > MAX_RELS) n_rel = MAX_RELS;

    float* ent_out  = (float*)d_out;
    float* user_out = (float*)d_out + (long)n_entities * DD;

    // Zero output (DMA fill) and counts scratch.
    cudaMemsetAsync(d_out, 0, (size_t)out_size * sizeof(float));
    void* counts_addr = nullptr;
    cudaGetSymbolAddress(&counts_addr, g_counts);
    cudaMemsetAsync(counts_addr, 0, (size_t)n_entities * sizeof(float));

    // Pass 1: counts. Pass 2: invert.
    {
        int threads = 256;
        int per_block = threads * 4;
        hgcn_count_kernel<<<(n_edges + per_block - 1) / per_block, threads>>>(ei, n_edges);
        hgcn_invert_kernel<<<(n_entities + 255) / 256, 256>>>(n_entities);
    }

    // Fused scatter, persistent-style grid sized to the chip (148 SMs).
    {
        int threads = 256;  // 8 warps
        // Work split ~ proportional to item counts (600K edges vs 1M nnz),
        // both multiples of SM count for even waves.
        int edge_blocks = 1184;   // 8 * 148
        int user_blocks = 1184;
        hgcn_scatter_kernel<<<edge_blocks + user_blocks, threads>>>(
            emb, ei, et, weight, irows, icols, ivals,
            ent_out, user_out, n_edges, n_rel, nnz, edge_blocks, user_blocks);
    }
}